// round 15
// baseline (speedup 1.0000x reference)
#include <cuda_runtime.h>
#include <cuda_bf16.h>
#include <cuda_fp16.h>
#include <cstdint>
#include <math.h>

#define B_   16
#define S_   2048
#define D_   128
#define H_   4
#define DH_  32
#define FF_  512
#define L_   4
#define OUT_ 30
#define M_   (B_*S_)   // 32768

// log2(e) / sqrt(32): folded into Q so softmax is a bare ex2
#define QSCALE 0.25506626866f

// ======================= low-level helpers =======================
__device__ __forceinline__ void mma16816(float* d, const uint32_t* a, const uint32_t* b) {
    asm volatile("mma.sync.aligned.m16n8k16.row.col.f32.bf16.bf16.f32 "
        "{%0,%1,%2,%3}, {%4,%5,%6,%7}, {%8,%9}, {%0,%1,%2,%3};"
        : "+f"(d[0]), "+f"(d[1]), "+f"(d[2]), "+f"(d[3])
        : "r"(a[0]), "r"(a[1]), "r"(a[2]), "r"(a[3]), "r"(b[0]), "r"(b[1]));
}
// f16 variant (for P@V: P/V in f16, fp32 accum)
__device__ __forceinline__ void mma16816h(float* d, const uint32_t* a, const uint32_t* b) {
    asm volatile("mma.sync.aligned.m16n8k16.row.col.f32.f16.f16.f32 "
        "{%0,%1,%2,%3}, {%4,%5,%6,%7}, {%8,%9}, {%0,%1,%2,%3};"
        : "+f"(d[0]), "+f"(d[1]), "+f"(d[2]), "+f"(d[3])
        : "r"(a[0]), "r"(a[1]), "r"(a[2]), "r"(a[3]), "r"(b[0]), "r"(b[1]));
}
__device__ __forceinline__ uint32_t packbf2(float x, float y) {
    __nv_bfloat162 p = __floats2bfloat162_rn(x, y);
    return *(uint32_t*)&p;
}
__device__ __forceinline__ uint32_t packhf2(float x, float y) {
    __half2 p = __floats2half2_rn(x, y);
    return *(uint32_t*)&p;
}
// pack two f32 into f16x2 (lo = first arg)
__device__ __forceinline__ uint32_t cvt2h(float lo, float hi) {
    uint32_t d; asm("cvt.rn.f16x2.f32 %0, %1, %2;" : "=r"(d) : "f"(hi), "f"(lo)); return d;
}
// 2^x on both f16 halves
__device__ __forceinline__ uint32_t ex2h2(uint32_t x) {
    uint32_t d; asm("ex2.approx.f16x2 %0, %1;" : "=r"(d) : "r"(x)); return d;
}
__device__ __forceinline__ uint32_t cvta_s(const void* p) {
    return (uint32_t)__cvta_generic_to_shared(p);
}
__device__ __forceinline__ void cp16(uint32_t dst, const void* src) {
    asm volatile("cp.async.cg.shared.global [%0], [%1], 16;" :: "r"(dst), "l"(src));
}
#define CP_COMMIT() asm volatile("cp.async.commit_group;" ::: "memory")
#define CP_WAIT(n)  asm volatile("cp.async.wait_group %0;" :: "n"(n) : "memory")
__device__ __forceinline__ void ldm_x4(uint32_t* r, uint32_t a) {
    asm volatile("ldmatrix.sync.aligned.m8n8.x4.shared.b16 {%0,%1,%2,%3}, [%4];"
        : "=r"(r[0]), "=r"(r[1]), "=r"(r[2]), "=r"(r[3]) : "r"(a));
}
__device__ __forceinline__ void ldm_x4t(uint32_t* r, uint32_t a) {
    asm volatile("ldmatrix.sync.aligned.m8n8.x4.trans.shared.b16 {%0,%1,%2,%3}, [%4];"
        : "=r"(r[0]), "=r"(r[1]), "=r"(r[2]), "=r"(r[3]) : "r"(a));
}

#define TST  40    // smem row stride (elements) for 32-wide tiles
#define TSTW 136   // smem row stride (elements) for 128-wide tiles

// ======================= scratch (device globals) =======================
__device__ __nv_bfloat16 g_qb[B_*H_*S_*DH_];
__device__ __nv_bfloat16 g_kb[B_*H_*S_*DH_];
__device__ __nv_bfloat16 g_vb[B_*H_*S_*DH_];   // holds f16 bits (P@V runs in f16)
__device__ __nv_bfloat16 g_attnb[M_*D_];
__device__ __nv_bfloat16 g_hb[M_*D_];
__device__ float         g_h[M_*D_];
__device__ __nv_bfloat16 g_wip[L_*3*D_*D_];
__device__ __nv_bfloat16 g_wout[L_*D_*D_];
__device__ __nv_bfloat16 g_wf1[L_*FF_*D_];
__device__ __nv_bfloat16 g_wf2[L_*D_*FF_];

// ======================= fp32 -> bf16 conversion =======================
__global__ __launch_bounds__(256) void cvt_kernel(const float* __restrict__ s,
                                                  __nv_bfloat16* __restrict__ d, int n) {
    int i = (blockIdx.x * 256 + threadIdx.x) * 4;
    if (i < n) {
        float4 v = *reinterpret_cast<const float4*>(s + i);
        *reinterpret_cast<uint2*>(d + i) = make_uint2(packbf2(v.x, v.y), packbf2(v.z, v.w));
    }
}

// ======================= QKV GEMM (layer 0 only; 3-stage pipeline) =======================
#define MM_SMEM 67072
__global__ __launch_bounds__(256)
void qkv_kernel(const __nv_bfloat16* __restrict__ A, const __nv_bfloat16* __restrict__ W,
                const float* __restrict__ bias,
                __nv_bfloat16* __restrict__ qo, __nv_bfloat16* __restrict__ ko,
                __nv_bfloat16* __restrict__ vo)
{
    extern __shared__ char smx[];
    const uint32_t sbase = cvta_s(smx);
    float* bias_s = (float*)(smx + 61440);

    const int t    = threadIdx.x;
    const int wid  = t >> 5;
    const int lane = t & 31;
    const int g    = lane >> 2;
    const int tq   = lane & 3;
    const int wm   = wid >> 2;
    const int wn   = wid & 3;
    const int row0 = blockIdx.y * 128;
    const int n0   = blockIdx.x * 128;
    const int K    = D_;

    if (t < 128) bias_s[t] = bias[n0 + t];

    auto sA = [&](int s) -> uint32_t { return sbase + s * 10240; };
    auto sB = [&](int s) -> uint32_t { return sbase + 30720 + s * 10240; };

    auto load_tile = [&](int kt, int stg) {
        const int k0 = kt << 5;
#pragma unroll
        for (int i = 0; i < 2; i++) {
            int id = t + (i << 8);
            int r = id >> 2, qq = id & 3;
            cp16(sA(stg) + r * (TST*2) + qq * 16, &A[(size_t)(row0 + r) * K + k0 + qq * 8]);
            cp16(sB(stg) + r * (TST*2) + qq * 16, &W[(size_t)(n0   + r) * K + k0 + qq * 8]);
        }
    };

    float acc[4][4][4];
#pragma unroll
    for (int mf = 0; mf < 4; mf++)
#pragma unroll
        for (int nf = 0; nf < 4; nf++)
#pragma unroll
            for (int e = 0; e < 4; e++) acc[mf][nf][e] = 0.f;

    load_tile(0, 0); CP_COMMIT();
    load_tile(1, 1); CP_COMMIT();

    const int aRow = wm * 64 + (lane & 15);
    const int aColX = (lane >> 4) * 8;
    const int bRow = wn * 32 + (lane & 7) + ((lane >> 4) << 3);
    const int bColX = ((lane >> 3) & 1) * 8;

    for (int kt = 0; kt < 4; kt++) {
        const int stg = kt % 3;
        if (kt < 3) CP_WAIT(1); else CP_WAIT(0);
        __syncthreads();
        if (kt + 2 < 4) { load_tile(kt + 2, (kt + 2) % 3); CP_COMMIT(); }

#pragma unroll
        for (int ks = 0; ks < 2; ks++) {
            const int kk = ks << 4;
            uint32_t af[4][4];
#pragma unroll
            for (int mf = 0; mf < 4; mf++)
                ldm_x4(af[mf], sA(stg) + ((aRow + mf * 16) * TST + kk + aColX) * 2);
            uint32_t bf[4][2];
#pragma unroll
            for (int pp = 0; pp < 2; pp++) {
                uint32_t r4[4];
                ldm_x4(r4, sB(stg) + ((bRow + pp * 16) * TST + kk + bColX) * 2);
                bf[pp*2][0] = r4[0]; bf[pp*2][1] = r4[1];
                bf[pp*2+1][0] = r4[2]; bf[pp*2+1][1] = r4[3];
            }
#pragma unroll
            for (int mf = 0; mf < 4; mf++)
#pragma unroll
                for (int nf = 0; nf < 4; nf++)
                    mma16816(acc[mf][nf], af[mf], bf[nf]);
        }
    }

#pragma unroll
    for (int mf = 0; mf < 4; mf++) {
        const int m0 = row0 + wm * 64 + mf * 16 + g;
        const int m1 = m0 + 8;
#pragma unroll
        for (int nf = 0; nf < 4; nf++) {
            const int c = wn * 32 + nf * 8 + tq * 2;
            float v0 = acc[mf][nf][0] + bias_s[c];
            float v1 = acc[mf][nf][1] + bias_s[c + 1];
            float v2 = acc[mf][nf][2] + bias_s[c];
            float v3 = acc[mf][nf][3] + bias_s[c + 1];
            __nv_bfloat16* dst = (blockIdx.x == 0) ? qo : ((blockIdx.x == 1) ? ko : vo);
            if (blockIdx.x == 0) { v0 *= QSCALE; v1 *= QSCALE; v2 *= QSCALE; v3 *= QSCALE; }
            const int hh = c >> 5, dd = c & 31;
            int b0i = m0 >> 11, s0i = m0 & 2047;
            int b1i = m1 >> 11, s1i = m1 & 2047;
            uint32_t p0, p1;
            if (blockIdx.x == 2) { p0 = packhf2(v0, v1); p1 = packhf2(v2, v3); }  // V -> f16
            else                 { p0 = packbf2(v0, v1); p1 = packbf2(v2, v3); }
            *reinterpret_cast<uint32_t*>(dst + ((size_t)(b0i * H_ + hh) * S_ + s0i) * DH_ + dd) = p0;
            *reinterpret_cast<uint32_t*>(dst + ((size_t)(b1i * H_ + hh) * S_ + s1i) * DH_ + dd) = p1;
        }
    }
}

// ======================= pipelined MMA flash attention (EXACT R10 — frozen) =======================
#define AT_SMEM 40960
#define NKV (S_ >> 6)
__global__ __launch_bounds__(256, 4)
void attn_kernel(const __nv_bfloat16* __restrict__ q, const __nv_bfloat16* __restrict__ k,
                 const __nv_bfloat16* __restrict__ v, __nv_bfloat16* __restrict__ out)
{
    extern __shared__ char smx[];
    const uint32_t sbase = cvta_s(smx);
    const uint32_t sQ = sbase;

    const int t    = threadIdx.x;
    const int wid  = t >> 5;
    const int lane = t & 31;
    const int g    = lane >> 2;
    const int tq   = lane & 3;
    const int bh   = blockIdx.y, b = bh >> 2, h = bh & 3;
    const int q0   = blockIdx.x * 128;

    auto sK = [&](int s) -> uint32_t { return sbase + 10240 + s * 10240; };
    auto sV = [&](int s) -> uint32_t { return sbase + 15360 + s * 10240; };

    auto load_kv = [&](int tile, int stg) {
        const int j0 = tile << 6;
        int r = t >> 2, qq = t & 3;
        cp16(sK(stg) + r * (TST*2) + qq * 16, &k[((size_t)bh * S_ + j0 + r) * DH_ + qq * 8]);
        cp16(sV(stg) + r * (TST*2) + qq * 16, &v[((size_t)bh * S_ + j0 + r) * DH_ + qq * 8]);
    };

    // prologue
#pragma unroll
    for (int i = 0; i < 2; i++) {
        int id = t + (i << 8);
        int r = id >> 2, qq = id & 3;
        cp16(sQ + r * (TST*2) + qq * 16, &q[((size_t)bh * S_ + q0 + r) * DH_ + qq * 8]);
    }
    load_kv(0, 0);
    CP_COMMIT();
    load_kv(1, 1);
    CP_COMMIT();

    float o[4][4];
    float ol[4];
#pragma unroll
    for (int nf = 0; nf < 4; nf++)
#pragma unroll
        for (int e = 0; e < 4; e++) o[nf][e] = 0.f;
#pragma unroll
    for (int e = 0; e < 4; e++) ol[e] = 0.f;

    uint32_t af2[2][4];
    const uint32_t vone = (lane < 4) ? 0x3C003C00u : 0u;

    const int aRow = wid * 16 + (lane & 15);
    const int aColX = (lane >> 4) * 8;
    const int bRow = (lane & 7) + ((lane >> 4) << 3);
    const int bColX = ((lane >> 3) & 1) * 8;
    const int vRow = (lane & 7) + (((lane >> 3) & 1) << 3);
    const int vColX = (lane >> 4) * 8;

    for (int it = 0; it < NKV; it++) {
        const int stg = it % 3;
        if (it < NKV - 1) CP_WAIT(1); else CP_WAIT(0);
        __syncthreads();
        if (it + 2 < NKV) { load_kv(it + 2, (it + 2) % 3); CP_COMMIT(); }

        if (it == 0) {
#pragma unroll
            for (int ks = 0; ks < 2; ks++)
                ldm_x4(af2[ks], sQ + (aRow * TST + ks * 16 + aColX) * 2);
        }

        float sc[8][4];
#pragma unroll
        for (int nf = 0; nf < 8; nf++)
#pragma unroll
            for (int e = 0; e < 4; e++) sc[nf][e] = 0.f;
#pragma unroll
        for (int ks = 0; ks < 2; ks++) {
            const int kk = ks << 4;
#pragma unroll
            for (int pp = 0; pp < 4; pp++) {
                uint32_t r4[4];
                ldm_x4(r4, sK(stg) + ((pp * 16 + bRow) * TST + kk + bColX) * 2);
                uint32_t b0[2] = { r4[0], r4[1] }, b1[2] = { r4[2], r4[3] };
                mma16816(sc[pp*2],   af2[ks], b0);
                mma16816(sc[pp*2+1], af2[ks], b1);
            }
        }

        uint32_t pb[8][2];
#pragma unroll
        for (int nf = 0; nf < 8; nf++) {
            pb[nf][0] = ex2h2(cvt2h(sc[nf][0], sc[nf][1]));
            pb[nf][1] = ex2h2(cvt2h(sc[nf][2], sc[nf][3]));
        }

#pragma unroll
        for (int kf = 0; kf < 4; kf++) {
            uint32_t a4[4] = { pb[2*kf][0], pb[2*kf][1], pb[2*kf+1][0], pb[2*kf+1][1] };
            uint32_t bones[2] = { vone, vone };
            mma16816h(ol, a4, bones);
#pragma unroll
            for (int pp = 0; pp < 2; pp++) {
                uint32_t r4[4];
                ldm_x4t(r4, sV(stg) + ((kf * 16 + vRow) * TST + pp * 16 + vColX) * 2);
                uint32_t b0[2] = { r4[0], r4[1] }, b1[2] = { r4[2], r4[3] };
                mma16816h(o[pp*2],   a4, b0);
                mma16816h(o[pp*2+1], a4, b1);
            }
        }
    }

    const float lg  = __shfl_sync(0xffffffffu, ol[0], lane & ~3);
    const float lg8 = __shfl_sync(0xffffffffu, ol[2], lane & ~3);
    const float inv0 = 1.f / lg;
    const float inv1 = 1.f / lg8;

    const int r0 = q0 + wid * 16 + g;
    const int r1 = r0 + 8;
#pragma unroll
    for (int nf = 0; nf < 4; nf++) {
        const int dd = nf * 8 + tq * 2;
        *reinterpret_cast<uint32_t*>(out + ((size_t)(b * S_ + r0)) * D_ + h * DH_ + dd) =
            packbf2(o[nf][0] * inv0, o[nf][1] * inv0);
        *reinterpret_cast<uint32_t*>(out + ((size_t)(b * S_ + r1)) * D_ + h * DH_ + dd) =
            packbf2(o[nf][2] * inv1, o[nf][3] * inv1);
    }
}

// ======================= fused out-proj + LN1 + FFN + LN2 [+ next-layer QKV] =======================
// Phase 2 restructured for occupancy: quarter-chunk (32 ff-cols) GEMM1->relu->GEMM2
// interleave drops acc1 liveness 64->16 regs; A-frags re-read from smem (no hoist).
// Targets 2 CTAs/SM via __launch_bounds__(256,2). Arithmetic identical to R14.
#define FF_SMEM 111104
template<int DO_QKV>
__global__ __launch_bounds__(256, 2)
void ffn2_kernel(const __nv_bfloat16* __restrict__ attnb,
                 const __nv_bfloat16* __restrict__ Wo, const float* __restrict__ ob,
                 const float* __restrict__ Rin,
                 const float* __restrict__ l1g, const float* __restrict__ l1b,
                 const __nv_bfloat16* __restrict__ W1, const float* __restrict__ b1,
                 const __nv_bfloat16* __restrict__ W2, const float* __restrict__ b2,
                 const float* __restrict__ l2g, const float* __restrict__ l2b,
                 const __nv_bfloat16* __restrict__ Wqkv, const float* __restrict__ qkvb,
                 __nv_bfloat16* __restrict__ qo, __nv_bfloat16* __restrict__ ko,
                 __nv_bfloat16* __restrict__ vo,
                 float* __restrict__ hOut)
{
    extern __shared__ char sm[];
    float* ob_s  = (float*)(sm + 104448);
    float* g1s   = (float*)(sm + 104960);
    float* bb1s  = (float*)(sm + 105472);
    float* b1s   = (float*)(sm + 105984);   // 512 floats
    float* b2s   = (float*)(sm + 108032);
    float* g2s   = (float*)(sm + 108544);
    float* bb2s  = (float*)(sm + 109056);
    float* qb_s  = (float*)(sm + 109568);   // 384 floats (qkv bias)

    const int t    = threadIdx.x;
    const int wid  = t >> 5;
    const int lane = t & 31;
    const int g    = lane >> 2;
    const int tq   = lane & 3;
    const int row0 = blockIdx.x * 128;

    const uint32_t sA  = cvta_s(sm);
    const uint32_t sWa = sA + 34816;   // Wo, then W2 chunks, then Wk
    const uint32_t sWb = sA + 69632;   // W1 chunks, then Wq/Wv

    auto loadW1 = [&](int c) {
#pragma unroll
        for (int i = 0; i < 8; i++) {
            int id = t + (i << 8);
            int r = id >> 4, cc = id & 15;
            cp16(sWb + (r * TSTW + cc * 8) * 2, &W1[(size_t)(c * 128 + r) * 128 + cc * 8]);
        }
    };
    auto loadW2 = [&](int c) {
#pragma unroll
        for (int i = 0; i < 8; i++) {
            int id = t + (i << 8);
            int r = id >> 4, cc = id & 15;
            cp16(sWa + (r * TSTW + cc * 8) * 2, &W2[(size_t)r * 512 + c * 128 + cc * 8]);
        }
    };
    auto loadWq = [&](int c, uint32_t dstbuf) {
#pragma unroll
        for (int i = 0; i < 8; i++) {
            int id = t + (i << 8);
            int r = id >> 4, cc = id & 15;
            cp16(dstbuf + (r * TSTW + cc * 8) * 2, &Wqkv[(size_t)(c * 128 + r) * 128 + cc * 8]);
        }
    };

    // ---- prologue: attnb + Wo (G1); W1[0] (G2); params ----
#pragma unroll
    for (int i = 0; i < 8; i++) {
        int id = t + (i << 8);
        int r = id >> 4, cc = id & 15;
        cp16(sA  + (r * TSTW + cc * 8) * 2, &attnb[(size_t)(row0 + r) * 128 + cc * 8]);
        cp16(sWa + (r * TSTW + cc * 8) * 2, &Wo[(size_t)r * 128 + cc * 8]);
    }
    CP_COMMIT();
    loadW1(0);
    CP_COMMIT();
    b1s[t] = b1[t]; b1s[t + 256] = b1[t + 256];
    if (t < 128) {
        ob_s[t] = ob[t]; g1s[t] = l1g[t]; bb1s[t] = l1b[t];
        b2s[t] = b2[t];  g2s[t] = l2g[t]; bb2s[t] = l2b[t];
    }
    if (DO_QKV && t < 128) {
        qb_s[t] = qkvb[t]; qb_s[t + 128] = qkvb[t + 128]; qb_s[t + 256] = qkvb[t + 256];
    }
    CP_WAIT(1);          // G1 done; G2 in flight
    __syncthreads();

    const int aRow = wid * 16 + (lane & 15);
    const int aColX = (lane >> 4) * 8;
    const int bRow = (lane & 7) + ((lane >> 4) << 3);
    const int bColX = ((lane >> 3) & 1) * 8;
    const int m0 = row0 + wid * 16 + g;
    const int m1 = m0 + 8;
    const int lm0 = wid * 16 + g;
    const int lm1 = lm0 + 8;

    float acc1[16][4];

    // ================= PHASE 1: out-projection (kf-outer, transient A-frags) =================
#pragma unroll
    for (int nf = 0; nf < 16; nf++)
#pragma unroll
        for (int e = 0; e < 4; e++) acc1[nf][e] = 0.f;
#pragma unroll
    for (int kf = 0; kf < 8; kf++) {
        uint32_t afq[4];
        ldm_x4(afq, sA + (aRow * TSTW + kf * 16 + aColX) * 2);
#pragma unroll
        for (int np = 0; np < 8; np++) {
            uint32_t r4[4];
            ldm_x4(r4, sWa + ((np * 16 + bRow) * TSTW + kf * 16 + bColX) * 2);
            uint32_t b0f[2] = { r4[0], r4[1] }, b1f[2] = { r4[2], r4[3] };
            mma16816(acc1[np*2],   afq, b0f);
            mma16816(acc1[np*2+1], afq, b1f);
        }
    }
    __syncthreads();
    loadW2(0); CP_COMMIT();                // G3 -> sWa (overlaps epilogue)

    // bias + residual(Rin) + LN1 -> hOut (fp32) + As (bf16)
    {
        float s0 = 0.f, sq0 = 0.f, s1 = 0.f, sq1 = 0.f;
#pragma unroll
        for (int nf = 0; nf < 16; nf++) {
            const int cc = nf * 8 + tq * 2;
            float2 r0 = *reinterpret_cast<const float2*>(Rin + (size_t)m0 * 128 + cc);
            float2 r1 = *reinterpret_cast<const float2*>(Rin + (size_t)m1 * 128 + cc);
            float v0 = acc1[nf][0] + ob_s[cc]     + r0.x;
            float v1 = acc1[nf][1] + ob_s[cc + 1] + r0.y;
            float v2 = acc1[nf][2] + ob_s[cc]     + r1.x;
            float v3 = acc1[nf][3] + ob_s[cc + 1] + r1.y;
            acc1[nf][0] = v0; acc1[nf][1] = v1; acc1[nf][2] = v2; acc1[nf][3] = v3;
            s0 += v0 + v1; sq0 += v0*v0 + v1*v1;
            s1 += v2 + v3; sq1 += v2*v2 + v3*v3;
        }
        s0  += __shfl_xor_sync(0xffffffffu, s0, 1);  s0  += __shfl_xor_sync(0xffffffffu, s0, 2);
        sq0 += __shfl_xor_sync(0xffffffffu, sq0, 1); sq0 += __shfl_xor_sync(0xffffffffu, sq0, 2);
        s1  += __shfl_xor_sync(0xffffffffu, s1, 1);  s1  += __shfl_xor_sync(0xffffffffu, s1, 2);
        sq1 += __shfl_xor_sync(0xffffffffu, sq1, 1); sq1 += __shfl_xor_sync(0xffffffffu, sq1, 2);
        float mean0 = s0 * (1.f/128.f);
        float mean1 = s1 * (1.f/128.f);
        float rstd0 = rsqrtf(sq0 * (1.f/128.f) - mean0*mean0 + 1e-5f);
        float rstd1 = rsqrtf(sq1 * (1.f/128.f) - mean1*mean1 + 1e-5f);
#pragma unroll
        for (int nf = 0; nf < 16; nf++) {
            const int cc = nf * 8 + tq * 2;
            float y0 = (acc1[nf][0] - mean0) * rstd0 * g1s[cc]   + bb1s[cc];
            float y1 = (acc1[nf][1] - mean0) * rstd0 * g1s[cc+1] + bb1s[cc+1];
            float y2 = (acc1[nf][2] - mean1) * rstd1 * g1s[cc]   + bb1s[cc];
            float y3 = (acc1[nf][3] - mean1) * rstd1 * g1s[cc+1] + bb1s[cc+1];
            *reinterpret_cast<float2*>(hOut + (size_t)m0 * 128 + cc) = make_float2(y0, y1);
            *reinterpret_cast<float2*>(hOut + (size_t)m1 * 128 + cc) = make_float2(y2, y3);
            asm volatile("st.shared.b32 [%0], %1;" :: "r"(sA + (lm0 * TSTW + cc) * 2), "r"(packbf2(y0, y1)));
            asm volatile("st.shared.b32 [%0], %1;" :: "r"(sA + (lm1 * TSTW + cc) * 2), "r"(packbf2(y2, y3)));
        }
    }
    __syncthreads();                       // As = LN1 output (bf16)

    // ================= PHASE 2: FFN, quarter-chunk interleave =================
    float acc2[16][4];
#pragma unroll
    for (int nf = 0; nf < 16; nf++)
#pragma unroll
        for (int e = 0; e < 4; e++) acc2[nf][e] = 0.f;

    for (int c = 0; c < 4; c++) {
        CP_WAIT(0);                        // W1[c] (sWb) + W2[c] (sWa) ready
        __syncthreads();

#pragma unroll
        for (int q = 0; q < 4; q++) {
            // GEMM1 quarter: 32 ff-cols (np = 2q, 2q+1)
            float acc1q[4][4];
#pragma unroll
            for (int nf = 0; nf < 4; nf++)
#pragma unroll
                for (int e = 0; e < 4; e++) acc1q[nf][e] = 0.f;
#pragma unroll
            for (int kf = 0; kf < 8; kf++) {
                uint32_t afq[4];
                ldm_x4(afq, sA + (aRow * TSTW + kf * 16 + aColX) * 2);
#pragma unroll
                for (int npq = 0; npq < 2; npq++) {
                    const int np = q * 2 + npq;
                    uint32_t r4[4];
                    ldm_x4(r4, sWb + ((np * 16 + bRow) * TSTW + kf * 16 + bColX) * 2);
                    uint32_t b0f[2] = { r4[0], r4[1] }, b1f[2] = { r4[2], r4[3] };
                    mma16816(acc1q[npq*2],   afq, b0f);
                    mma16816(acc1q[npq*2+1], afq, b1f);
                }
            }
            // relu + bias -> GEMM2 A k-frags for this quarter
            uint32_t a1q[2][4];
#pragma unroll
            for (int npq = 0; npq < 2; npq++) {
                const int np = q * 2 + npq;
                const int col = c * 128 + np * 16 + tq * 2;
                float e0 = fmaxf(acc1q[npq*2][0]   + b1s[col],     0.f);
                float e1 = fmaxf(acc1q[npq*2][1]   + b1s[col + 1], 0.f);
                float e2 = fmaxf(acc1q[npq*2][2]   + b1s[col],     0.f);
                float e3 = fmaxf(acc1q[npq*2][3]   + b1s[col + 1], 0.f);
                float o0 = fmaxf(acc1q[npq*2+1][0] + b1s[col + 8], 0.f);
                float o1 = fmaxf(acc1q[npq*2+1][1] + b1s[col + 9], 0.f);
                float o2 = fmaxf(acc1q[npq*2+1][2] + b1s[col + 8], 0.f);
                float o3 = fmaxf(acc1q[npq*2+1][3] + b1s[col + 9], 0.f);
                a1q[npq][0] = packbf2(e0, e1); a1q[npq][1] = packbf2(e2, e3);
                a1q[npq][2] = packbf2(o0, o1); a1q[npq][3] = packbf2(o2, o3);
            }
            // GEMM2 quarter: accumulate into acc2
#pragma unroll
            for (int npq = 0; npq < 2; npq++) {
                const int kf2 = q * 2 + npq;
#pragma unroll
                for (int np2 = 0; np2 < 8; np2++) {
                    uint32_t r4[4];
                    ldm_x4(r4, sWa + ((np2 * 16 + bRow) * TSTW + kf2 * 16 + bColX) * 2);
                    uint32_t b0f[2] = { r4[0], r4[1] }, b1f[2] = { r4[2], r4[3] };
                    mma16816(acc2[np2*2],   a1q[npq], b0f);
                    mma16816(acc2[np2*2+1], a1q[npq], b1f);
                }
            }
        }
        __syncthreads();                   // all warps done with W1[c], W2[c]
        if (c < 3) {
            loadW1(c + 1); CP_COMMIT();
            loadW2(c + 1); CP_COMMIT();
        } else if (DO_QKV) {
            loadWq(0, sWb); CP_COMMIT();   // Wq
            loadWq(1, sWa); CP_COMMIT();   // Wk
        }
    }

    // ---- bias + residual(h=LN1) + LN2 -> hOut (+ As bf16 if QKV) ----
    {
        float s0 = 0.f, sq0 = 0.f, s1 = 0.f, sq1 = 0.f;
#pragma unroll
        for (int nf = 0; nf < 16; nf++) {
            const int cc = nf * 8 + tq * 2;
            float2 r0 = *reinterpret_cast<const float2*>(hOut + (size_t)m0 * 128 + cc);
            float2 r1 = *reinterpret_cast<const float2*>(hOut + (size_t)m1 * 128 + cc);
            float v0 = acc2[nf][0] + b2s[cc]     + r0.x;
            float v1 = acc2[nf][1] + b2s[cc + 1] + r0.y;
            float v2 = acc2[nf][2] + b2s[cc]     + r1.x;
            float v3 = acc2[nf][3] + b2s[cc + 1] + r1.y;
            acc2[nf][0] = v0; acc2[nf][1] = v1; acc2[nf][2] = v2; acc2[nf][3] = v3;
            s0 += v0 + v1; sq0 += v0*v0 + v1*v1;
            s1 += v2 + v3; sq1 += v2*v2 + v3*v3;
        }
        s0  += __shfl_xor_sync(0xffffffffu, s0, 1);  s0  += __shfl_xor_sync(0xffffffffu, s0, 2);
        sq0 += __shfl_xor_sync(0xffffffffu, sq0, 1); sq0 += __shfl_xor_sync(0xffffffffu, sq0, 2);
        s1  += __shfl_xor_sync(0xffffffffu, s1, 1);  s1  += __shfl_xor_sync(0xffffffffu, s1, 2);
        sq1 += __shfl_xor_sync(0xffffffffu, sq1, 1); sq1 += __shfl_xor_sync(0xffffffffu, sq1, 2);
        float mean0 = s0 * (1.f/128.f);
        float mean1 = s1 * (1.f/128.f);
        float rstd0 = rsqrtf(sq0 * (1.f/128.f) - mean0*mean0 + 1e-5f);
        float rstd1 = rsqrtf(sq1 * (1.f/128.f) - mean1*mean1 + 1e-5f);
#pragma unroll
        for (int nf = 0; nf < 16; nf++) {
            const int cc = nf * 8 + tq * 2;
            float y0 = (acc2[nf][0] - mean0) * rstd0 * g2s[cc]   + bb2s[cc];
            float y1 = (acc2[nf][1] - mean0) * rstd0 * g2s[cc+1] + bb2s[cc+1];
            float y2 = (acc2[nf][2] - mean1) * rstd1 * g2s[cc]   + bb2s[cc];
            float y3 = (acc2[nf][3] - mean1) * rstd1 * g2s[cc+1] + bb2s[cc+1];
            *reinterpret_cast<float2*>(hOut + (size_t)m0 * 128 + cc) = make_float2(y0, y1);
            *reinterpret_cast<float2*>(hOut + (size_t)m1 * 128 + cc) = make_float2(y2, y3);
            if (DO_QKV) {
                asm volatile("st.shared.b32 [%0], %1;" :: "r"(sA + (lm0 * TSTW + cc) * 2), "r"(packbf2(y0, y1)));
                asm volatile("st.shared.b32 [%0], %1;" :: "r"(sA + (lm1 * TSTW + cc) * 2), "r"(packbf2(y2, y3)));
            }
        }
    }
    if (!DO_QKV) return;
    __syncthreads();                       // As = LN2 output (bf16)

    // ================= PHASE 3: next-layer QKV (kf-outer, transient A-frags) =================
    const int b0i = m0 >> 11, s0i = m0 & 2047;
    const int b1i = m1 >> 11, s1i = m1 & 2047;

#pragma unroll
    for (int c3 = 0; c3 < 3; c3++) {
        if (c3 < 2) CP_WAIT(1); else CP_WAIT(0);   // chunk c3 ready
        __syncthreads();
        const uint32_t wbuf = (c3 == 1) ? sWa : sWb;

#pragma unroll
        for (int nf = 0; nf < 16; nf++)
#pragma unroll
            for (int e = 0; e < 4; e++) acc1[nf][e] = 0.f;
#pragma unroll
        for (int kf = 0; kf < 8; kf++) {
            uint32_t afq[4];
            ldm_x4(afq, sA + (aRow * TSTW + kf * 16 + aColX) * 2);
#pragma unroll
            for (int np = 0; np < 8; np++) {
                uint32_t r4[4];
                ldm_x4(r4, wbuf + ((np * 16 + bRow) * TSTW + kf * 16 + bColX) * 2);
                uint32_t b0f[2] = { r4[0], r4[1] }, b1f[2] = { r4[2], r4[3] };
                mma16816(acc1[np*2],   afq, b0f);
                mma16816(acc1[np*2+1], afq, b1f);
            }
        }
        __syncthreads();
        if (c3 == 0) { loadWq(2, sWb); CP_COMMIT(); }   // Wv -> sWb during q epilogue

        __nv_bfloat16* dst = (c3 == 0) ? qo : ((c3 == 1) ? ko : vo);
#pragma unroll
        for (int nf = 0; nf < 16; nf++) {
            const int cc = nf * 8 + tq * 2;
            float v0 = acc1[nf][0] + qb_s[c3 * 128 + cc];
            float v1 = acc1[nf][1] + qb_s[c3 * 128 + cc + 1];
            float v2 = acc1[nf][2] + qb_s[c3 * 128 + cc];
            float v3 = acc1[nf][3] + qb_s[c3 * 128 + cc + 1];
            if (c3 == 0) { v0 *= QSCALE; v1 *= QSCALE; v2 *= QSCALE; v3 *= QSCALE; }
            const int hh = cc >> 5, dd = cc & 31;
            uint32_t p0, p1;
            if (c3 == 2) { p0 = packhf2(v0, v1); p1 = packhf2(v2, v3); }
            else         { p0 = packbf2(v0, v1); p1 = packbf2(v2, v3); }
            *reinterpret_cast<uint32_t*>(dst + ((size_t)(b0i * H_ + hh) * S_ + s0i) * DH_ + dd) = p0;
            *reinterpret_cast<uint32_t*>(dst + ((size_t)(b1i * H_ + hh) * S_ + s1i) * DH_ + dd) = p1;
        }
    }
}

// ======================= Head: FC -> softmax -> rebalance =======================
__global__ __launch_bounds__(512)
void head_kernel(const float* __restrict__ hbuf, const float* __restrict__ fcw,
                 const float* __restrict__ fcb, float* __restrict__ out)
{
    __shared__ float logits[B_][OUT_];
    const int t = threadIdx.x;
    if (t < B_ * OUT_) {
        int b = t / OUT_;
        int o = t % OUT_;
        const float* hr = hbuf + ((size_t)(b * S_ + (S_ - 1))) * D_;
        float acc = fcb[o];
        for (int d = 0; d < D_; d++) acc += hr[d] * fcw[o * D_ + d];
        logits[b][o] = acc;
    }
    __syncthreads();
    if (t < B_) {
        const float UB = 0.3f, LB = 0.0f;
        float wv[OUT_], old[OUT_], wc[OUT_], res[OUT_];
        float mx = -1e30f;
        for (int o = 0; o < OUT_; o++) mx = fmaxf(mx, logits[t][o]);
        float sum = 0.f;
        for (int o = 0; o < OUT_; o++) { wv[o] = expf(logits[t][o] - mx); sum += wv[o]; }
        float inv = 1.f / sum;
        for (int o = 0; o < OUT_; o++) wv[o] *= inv;
        bool done = false;
        for (int o = 0; o < OUT_; o++) {
            old[o] = wv[o];
            wc[o]  = fminf(fmaxf(wv[o], LB), UB);
            res[o] = wv[o];
        }
        for (int it = 0; it < 16; it++) {
            float leftover = 0.f;
            for (int o = 0; o < OUT_; o++) leftover += old[o] - wc[o];
            float denom = 0.f;
            float noms[OUT_];
            for (int o = 0; o < OUT_; o++) {
                noms[o] = (wc[o] != UB) ? wc[o] : 0.f;
                denom += noms[o];
            }
            if (denom == 0.f) denom = 1.f;
            float cand[OUT_];
            bool any = false;
            for (int o = 0; o < OUT_; o++) {
                cand[o] = wc[o] + leftover * noms[o] / denom;
                if (cand[o] > UB) any = true;
            }
            if (!done)
                for (int o = 0; o < OUT_; o++) res[o] = cand[o];
            done = done || !any;
            if (!done) {
                for (int o = 0; o < OUT_; o++) {
                    old[o] = cand[o];
                    wc[o]  = fminf(fmaxf(cand[o], LB), UB);
                }
            }
        }
        for (int o = 0; o < OUT_; o++) out[t * OUT_ + o] = res[o];
    }
}

// ======================= launch =======================
extern "C" void kernel_launch(void* const* d_in, const int* in_sizes, int n_in,
                              void* d_out, int out_size)
{
    const float* x   = (const float*)d_in[0];
    const float* ipw = (const float*)d_in[1];
    const float* ipb = (const float*)d_in[2];
    const float* ow  = (const float*)d_in[3];
    const float* ob  = (const float*)d_in[4];
    const float* l1g = (const float*)d_in[5];
    const float* l1b = (const float*)d_in[6];
    const float* f1w = (const float*)d_in[7];
    const float* f1b = (const float*)d_in[8];
    const float* f2w = (const float*)d_in[9];
    const float* f2b = (const float*)d_in[10];
    const float* l2g = (const float*)d_in[11];
    const float* l2b = (const float*)d_in[12];
    const float* fcw = (const float*)d_in[13];
    const float* fcb = (const float*)d_in[14];

    __nv_bfloat16 *qb, *kb, *vb, *attnb, *hb, *wip, *wout, *wf1, *wf2;
    float *h;
    cudaGetSymbolAddress((void**)&qb,    g_qb);
    cudaGetSymbolAddress((void**)&kb,    g_kb);
    cudaGetSymbolAddress((void**)&vb,    g_vb);
    cudaGetSymbolAddress((void**)&attnb, g_attnb);
    cudaGetSymbolAddress((void**)&hb,    g_hb);
    cudaGetSymbolAddress((void**)&h,     g_h);
    cudaGetSymbolAddress((void**)&wip,   g_wip);
    cudaGetSymbolAddress((void**)&wout,  g_wout);
    cudaGetSymbolAddress((void**)&wf1,   g_wf1);
    cudaGetSymbolAddress((void**)&wf2,   g_wf2);

    cudaFuncSetAttribute(qkv_kernel,     cudaFuncAttributeMaxDynamicSharedMemorySize, MM_SMEM);
    cudaFuncSetAttribute(attn_kernel,    cudaFuncAttributeMaxDynamicSharedMemorySize, AT_SMEM);
    cudaFuncSetAttribute(ffn2_kernel<0>, cudaFuncAttributeMaxDynamicSharedMemorySize, FF_SMEM);
    cudaFuncSetAttribute(ffn2_kernel<1>, cudaFuncAttributeMaxDynamicSharedMemorySize, FF_SMEM);

    cvt_kernel<<<(L_*3*D_*D_)/1024, 256>>>(ipw, wip, L_*3*D_*D_);   // launch 0
    cvt_kernel<<<(M_*D_)/1024,      256>>>(x,   hb,  M_*D_);        // launch 1

    // layer-0 QKV (from x)
    qkv_kernel<<<dim3(3, M_/128), 256, MM_SMEM>>>(
        hb, wip, ipb, qb, kb, vb);

    for (int l = 0; l < L_; l++) {
        const float* hinF = (l == 0) ? x : h;

        // flash attention (launch 3 on first layer — profiling anchor)
        attn_kernel<<<dim3(S_/128, B_*H_), 256, AT_SMEM>>>(qb, kb, vb, attnb);

        if (l == 0) {
            cvt_kernel<<<(L_*D_*D_)/1024,  256>>>(ow,  wout, L_*D_*D_);
            cvt_kernel<<<(L_*FF_*D_)/1024, 256>>>(f1w, wf1, L_*FF_*D_);
            cvt_kernel<<<(L_*D_*FF_)/1024, 256>>>(f2w, wf2, L_*D_*FF_);
        }

        if (l < 3) {
            // fused out-proj + LN1 + FFN + LN2 + next-layer QKV
            ffn2_kernel<1><<<M_/128, 256, FF_SMEM>>>(
                attnb, wout + (size_t)l*D_*D_, ob + (size_t)l*D_,
                hinF, l1g + (size_t)l*D_, l1b + (size_t)l*D_,
                wf1 + (size_t)l*FF_*D_, f1b + (size_t)l*FF_,
                wf2 + (size_t)l*D_*FF_, f2b + (size_t)l*D_,
                l2g + (size_t)l*D_, l2b + (size_t)l*D_,
                wip + (size_t)(l+1)*3*D_*D_, ipb + (size_t)(l+1)*3*D_,
                qb, kb, vb, h);
        } else {
            ffn2_kernel<0><<<M_/128, 256, FF_SMEM>>>(
                attnb, wout + (size_t)l*D_*D_, ob + (size_t)l*D_,
                hinF, l1g + (size_t)l*D_, l1b + (size_t)l*D_,
                wf1 + (size_t)l*FF_*D_, f1b + (size_t)l*FF_,
                wf2 + (size_t)l*D_*FF_, f2b + (size_t)l*D_,
                l2g + (size_t)l*D_, l2b + (size_t)l*D_,
                nullptr, nullptr, nullptr, nullptr, nullptr, h);
        }
    }

    head_kernel<<<1, 512>>>(h, fcw, fcb, (float*)d_out);
}

// round 16
// speedup vs baseline: 1.0595x; 1.0595x over previous
#include <cuda_runtime.h>
#include <cuda_bf16.h>
#include <cuda_fp16.h>
#include <cstdint>
#include <math.h>

#define B_   16
#define S_   2048
#define D_   128
#define H_   4
#define DH_  32
#define FF_  512
#define L_   4
#define OUT_ 30
#define M_   (B_*S_)   // 32768

// log2(e) / sqrt(32): folded into Q so softmax is a bare ex2
#define QSCALE 0.25506626866f

// ======================= low-level helpers =======================
__device__ __forceinline__ void mma16816(float* d, const uint32_t* a, const uint32_t* b) {
    asm volatile("mma.sync.aligned.m16n8k16.row.col.f32.bf16.bf16.f32 "
        "{%0,%1,%2,%3}, {%4,%5,%6,%7}, {%8,%9}, {%0,%1,%2,%3};"
        : "+f"(d[0]), "+f"(d[1]), "+f"(d[2]), "+f"(d[3])
        : "r"(a[0]), "r"(a[1]), "r"(a[2]), "r"(a[3]), "r"(b[0]), "r"(b[1]));
}
// f16 variant (for P@V: P/V in f16, fp32 accum)
__device__ __forceinline__ void mma16816h(float* d, const uint32_t* a, const uint32_t* b) {
    asm volatile("mma.sync.aligned.m16n8k16.row.col.f32.f16.f16.f32 "
        "{%0,%1,%2,%3}, {%4,%5,%6,%7}, {%8,%9}, {%0,%1,%2,%3};"
        : "+f"(d[0]), "+f"(d[1]), "+f"(d[2]), "+f"(d[3])
        : "r"(a[0]), "r"(a[1]), "r"(a[2]), "r"(a[3]), "r"(b[0]), "r"(b[1]));
}
__device__ __forceinline__ uint32_t packbf2(float x, float y) {
    __nv_bfloat162 p = __floats2bfloat162_rn(x, y);
    return *(uint32_t*)&p;
}
__device__ __forceinline__ uint32_t packhf2(float x, float y) {
    __half2 p = __floats2half2_rn(x, y);
    return *(uint32_t*)&p;
}
// pack two f32 into f16x2 (lo = first arg)
__device__ __forceinline__ uint32_t cvt2h(float lo, float hi) {
    uint32_t d; asm("cvt.rn.f16x2.f32 %0, %1, %2;" : "=r"(d) : "f"(hi), "f"(lo)); return d;
}
// 2^x on both f16 halves
__device__ __forceinline__ uint32_t ex2h2(uint32_t x) {
    uint32_t d; asm("ex2.approx.f16x2 %0, %1;" : "=r"(d) : "r"(x)); return d;
}
__device__ __forceinline__ uint32_t cvta_s(const void* p) {
    return (uint32_t)__cvta_generic_to_shared(p);
}
__device__ __forceinline__ void cp16(uint32_t dst, const void* src) {
    asm volatile("cp.async.cg.shared.global [%0], [%1], 16;" :: "r"(dst), "l"(src));
}
#define CP_COMMIT() asm volatile("cp.async.commit_group;" ::: "memory")
#define CP_WAIT(n)  asm volatile("cp.async.wait_group %0;" :: "n"(n) : "memory")
__device__ __forceinline__ void ldm_x4(uint32_t* r, uint32_t a) {
    asm volatile("ldmatrix.sync.aligned.m8n8.x4.shared.b16 {%0,%1,%2,%3}, [%4];"
        : "=r"(r[0]), "=r"(r[1]), "=r"(r[2]), "=r"(r[3]) : "r"(a));
}
__device__ __forceinline__ void ldm_x4t(uint32_t* r, uint32_t a) {
    asm volatile("ldmatrix.sync.aligned.m8n8.x4.trans.shared.b16 {%0,%1,%2,%3}, [%4];"
        : "=r"(r[0]), "=r"(r[1]), "=r"(r[2]), "=r"(r[3]) : "r"(a));
}

#define TST  40    // smem row stride (elements) for 32-wide tiles
#define TSTW 136   // smem row stride (elements) for 128-wide tiles

// ======================= scratch (device globals) =======================
__device__ __nv_bfloat16 g_qb[B_*H_*S_*DH_];
__device__ __nv_bfloat16 g_kb[B_*H_*S_*DH_];
__device__ __nv_bfloat16 g_vb[B_*H_*S_*DH_];   // holds f16 bits (P@V runs in f16)
__device__ __nv_bfloat16 g_attnb[M_*D_];
__device__ __nv_bfloat16 g_hb[M_*D_];
__device__ float         g_h[M_*D_];
__device__ __nv_bfloat16 g_wip[L_*3*D_*D_];
__device__ __nv_bfloat16 g_wout[L_*D_*D_];
__device__ __nv_bfloat16 g_wf1[L_*FF_*D_];
__device__ __nv_bfloat16 g_wf2[L_*D_*FF_];

// ======================= fp32 -> bf16 conversion (x) =======================
__global__ __launch_bounds__(256) void cvt_kernel(const float* __restrict__ s,
                                                  __nv_bfloat16* __restrict__ d, int n) {
    int i = (blockIdx.x * 256 + threadIdx.x) * 4;
    if (i < n) {
        float4 v = *reinterpret_cast<const float4*>(s + i);
        *reinterpret_cast<uint2*>(d + i) = make_uint2(packbf2(v.x, v.y), packbf2(v.z, v.w));
    }
}

// ======================= batched weight conversion (all 4 tensors, 1 launch) =======================
#define NW0 (L_*3*D_*D_)          // 196608
#define NW1 (L_*D_*D_)            // 65536
#define NW2 (L_*FF_*D_)           // 262144
#define NW3 (L_*D_*FF_)           // 262144
__global__ __launch_bounds__(256)
void cvtw_kernel(const float* __restrict__ s0, __nv_bfloat16* __restrict__ d0,
                 const float* __restrict__ s1, __nv_bfloat16* __restrict__ d1,
                 const float* __restrict__ s2, __nv_bfloat16* __restrict__ d2,
                 const float* __restrict__ s3, __nv_bfloat16* __restrict__ d3)
{
    int i = (blockIdx.x * 256 + threadIdx.x) * 4;
    const float* s; __nv_bfloat16* d; int off;
    if      (i < NW0)             { s = s0; d = d0; off = 0; }
    else if (i < NW0+NW1)         { s = s1; d = d1; off = NW0; }
    else if (i < NW0+NW1+NW2)     { s = s2; d = d2; off = NW0+NW1; }
    else                          { s = s3; d = d3; off = NW0+NW1+NW2; }
    int j = i - off;
    float4 v = *reinterpret_cast<const float4*>(s + j);
    *reinterpret_cast<uint2*>(d + j) = make_uint2(packbf2(v.x, v.y), packbf2(v.z, v.w));
}

// ======================= QKV GEMM (layer 0 only; 3-stage pipeline) =======================
#define MM_SMEM 67072
__global__ __launch_bounds__(256)
void qkv_kernel(const __nv_bfloat16* __restrict__ A, const __nv_bfloat16* __restrict__ W,
                const float* __restrict__ bias,
                __nv_bfloat16* __restrict__ qo, __nv_bfloat16* __restrict__ ko,
                __nv_bfloat16* __restrict__ vo)
{
    extern __shared__ char smx[];
    const uint32_t sbase = cvta_s(smx);
    float* bias_s = (float*)(smx + 61440);

    const int t    = threadIdx.x;
    const int wid  = t >> 5;
    const int lane = t & 31;
    const int g    = lane >> 2;
    const int tq   = lane & 3;
    const int wm   = wid >> 2;
    const int wn   = wid & 3;
    const int row0 = blockIdx.y * 128;
    const int n0   = blockIdx.x * 128;
    const int K    = D_;

    if (t < 128) bias_s[t] = bias[n0 + t];

    auto sA = [&](int s) -> uint32_t { return sbase + s * 10240; };
    auto sB = [&](int s) -> uint32_t { return sbase + 30720 + s * 10240; };

    auto load_tile = [&](int kt, int stg) {
        const int k0 = kt << 5;
#pragma unroll
        for (int i = 0; i < 2; i++) {
            int id = t + (i << 8);
            int r = id >> 2, qq = id & 3;
            cp16(sA(stg) + r * (TST*2) + qq * 16, &A[(size_t)(row0 + r) * K + k0 + qq * 8]);
            cp16(sB(stg) + r * (TST*2) + qq * 16, &W[(size_t)(n0   + r) * K + k0 + qq * 8]);
        }
    };

    float acc[4][4][4];
#pragma unroll
    for (int mf = 0; mf < 4; mf++)
#pragma unroll
        for (int nf = 0; nf < 4; nf++)
#pragma unroll
            for (int e = 0; e < 4; e++) acc[mf][nf][e] = 0.f;

    load_tile(0, 0); CP_COMMIT();
    load_tile(1, 1); CP_COMMIT();

    const int aRow = wm * 64 + (lane & 15);
    const int aColX = (lane >> 4) * 8;
    const int bRow = wn * 32 + (lane & 7) + ((lane >> 4) << 3);
    const int bColX = ((lane >> 3) & 1) * 8;

    for (int kt = 0; kt < 4; kt++) {
        const int stg = kt % 3;
        if (kt < 3) CP_WAIT(1); else CP_WAIT(0);
        __syncthreads();
        if (kt + 2 < 4) { load_tile(kt + 2, (kt + 2) % 3); CP_COMMIT(); }

#pragma unroll
        for (int ks = 0; ks < 2; ks++) {
            const int kk = ks << 4;
            uint32_t af[4][4];
#pragma unroll
            for (int mf = 0; mf < 4; mf++)
                ldm_x4(af[mf], sA(stg) + ((aRow + mf * 16) * TST + kk + aColX) * 2);
            uint32_t bf[4][2];
#pragma unroll
            for (int pp = 0; pp < 2; pp++) {
                uint32_t r4[4];
                ldm_x4(r4, sB(stg) + ((bRow + pp * 16) * TST + kk + bColX) * 2);
                bf[pp*2][0] = r4[0]; bf[pp*2][1] = r4[1];
                bf[pp*2+1][0] = r4[2]; bf[pp*2+1][1] = r4[3];
            }
#pragma unroll
            for (int mf = 0; mf < 4; mf++)
#pragma unroll
                for (int nf = 0; nf < 4; nf++)
                    mma16816(acc[mf][nf], af[mf], bf[nf]);
        }
    }

#pragma unroll
    for (int mf = 0; mf < 4; mf++) {
        const int m0 = row0 + wm * 64 + mf * 16 + g;
        const int m1 = m0 + 8;
#pragma unroll
        for (int nf = 0; nf < 4; nf++) {
            const int c = wn * 32 + nf * 8 + tq * 2;
            float v0 = acc[mf][nf][0] + bias_s[c];
            float v1 = acc[mf][nf][1] + bias_s[c + 1];
            float v2 = acc[mf][nf][2] + bias_s[c];
            float v3 = acc[mf][nf][3] + bias_s[c + 1];
            __nv_bfloat16* dst = (blockIdx.x == 0) ? qo : ((blockIdx.x == 1) ? ko : vo);
            if (blockIdx.x == 0) { v0 *= QSCALE; v1 *= QSCALE; v2 *= QSCALE; v3 *= QSCALE; }
            const int hh = c >> 5, dd = c & 31;
            int b0i = m0 >> 11, s0i = m0 & 2047;
            int b1i = m1 >> 11, s1i = m1 & 2047;
            uint32_t p0, p1;
            if (blockIdx.x == 2) { p0 = packhf2(v0, v1); p1 = packhf2(v2, v3); }  // V -> f16
            else                 { p0 = packbf2(v0, v1); p1 = packbf2(v2, v3); }
            *reinterpret_cast<uint32_t*>(dst + ((size_t)(b0i * H_ + hh) * S_ + s0i) * DH_ + dd) = p0;
            *reinterpret_cast<uint32_t*>(dst + ((size_t)(b1i * H_ + hh) * S_ + s1i) * DH_ + dd) = p1;
        }
    }
}

// ======================= pipelined MMA flash attention (EXACT R10 — frozen) =======================
#define AT_SMEM 40960
#define NKV (S_ >> 6)
__global__ __launch_bounds__(256, 4)
void attn_kernel(const __nv_bfloat16* __restrict__ q, const __nv_bfloat16* __restrict__ k,
                 const __nv_bfloat16* __restrict__ v, __nv_bfloat16* __restrict__ out)
{
    extern __shared__ char smx[];
    const uint32_t sbase = cvta_s(smx);
    const uint32_t sQ = sbase;

    const int t    = threadIdx.x;
    const int wid  = t >> 5;
    const int lane = t & 31;
    const int g    = lane >> 2;
    const int tq   = lane & 3;
    const int bh   = blockIdx.y, b = bh >> 2, h = bh & 3;
    const int q0   = blockIdx.x * 128;

    auto sK = [&](int s) -> uint32_t { return sbase + 10240 + s * 10240; };
    auto sV = [&](int s) -> uint32_t { return sbase + 15360 + s * 10240; };

    auto load_kv = [&](int tile, int stg) {
        const int j0 = tile << 6;
        int r = t >> 2, qq = t & 3;
        cp16(sK(stg) + r * (TST*2) + qq * 16, &k[((size_t)bh * S_ + j0 + r) * DH_ + qq * 8]);
        cp16(sV(stg) + r * (TST*2) + qq * 16, &v[((size_t)bh * S_ + j0 + r) * DH_ + qq * 8]);
    };

    // prologue
#pragma unroll
    for (int i = 0; i < 2; i++) {
        int id = t + (i << 8);
        int r = id >> 2, qq = id & 3;
        cp16(sQ + r * (TST*2) + qq * 16, &q[((size_t)bh * S_ + q0 + r) * DH_ + qq * 8]);
    }
    load_kv(0, 0);
    CP_COMMIT();
    load_kv(1, 1);
    CP_COMMIT();

    float o[4][4];
    float ol[4];
#pragma unroll
    for (int nf = 0; nf < 4; nf++)
#pragma unroll
        for (int e = 0; e < 4; e++) o[nf][e] = 0.f;
#pragma unroll
    for (int e = 0; e < 4; e++) ol[e] = 0.f;

    uint32_t af2[2][4];
    const uint32_t vone = (lane < 4) ? 0x3C003C00u : 0u;

    const int aRow = wid * 16 + (lane & 15);
    const int aColX = (lane >> 4) * 8;
    const int bRow = (lane & 7) + ((lane >> 4) << 3);
    const int bColX = ((lane >> 3) & 1) * 8;
    const int vRow = (lane & 7) + (((lane >> 3) & 1) << 3);
    const int vColX = (lane >> 4) * 8;

    for (int it = 0; it < NKV; it++) {
        const int stg = it % 3;
        if (it < NKV - 1) CP_WAIT(1); else CP_WAIT(0);
        __syncthreads();
        if (it + 2 < NKV) { load_kv(it + 2, (it + 2) % 3); CP_COMMIT(); }

        if (it == 0) {
#pragma unroll
            for (int ks = 0; ks < 2; ks++)
                ldm_x4(af2[ks], sQ + (aRow * TST + ks * 16 + aColX) * 2);
        }

        float sc[8][4];
#pragma unroll
        for (int nf = 0; nf < 8; nf++)
#pragma unroll
            for (int e = 0; e < 4; e++) sc[nf][e] = 0.f;
#pragma unroll
        for (int ks = 0; ks < 2; ks++) {
            const int kk = ks << 4;
#pragma unroll
            for (int pp = 0; pp < 4; pp++) {
                uint32_t r4[4];
                ldm_x4(r4, sK(stg) + ((pp * 16 + bRow) * TST + kk + bColX) * 2);
                uint32_t b0[2] = { r4[0], r4[1] }, b1[2] = { r4[2], r4[3] };
                mma16816(sc[pp*2],   af2[ks], b0);
                mma16816(sc[pp*2+1], af2[ks], b1);
            }
        }

        uint32_t pb[8][2];
#pragma unroll
        for (int nf = 0; nf < 8; nf++) {
            pb[nf][0] = ex2h2(cvt2h(sc[nf][0], sc[nf][1]));
            pb[nf][1] = ex2h2(cvt2h(sc[nf][2], sc[nf][3]));
        }

#pragma unroll
        for (int kf = 0; kf < 4; kf++) {
            uint32_t a4[4] = { pb[2*kf][0], pb[2*kf][1], pb[2*kf+1][0], pb[2*kf+1][1] };
            uint32_t bones[2] = { vone, vone };
            mma16816h(ol, a4, bones);
#pragma unroll
            for (int pp = 0; pp < 2; pp++) {
                uint32_t r4[4];
                ldm_x4t(r4, sV(stg) + ((kf * 16 + vRow) * TST + pp * 16 + vColX) * 2);
                uint32_t b0[2] = { r4[0], r4[1] }, b1[2] = { r4[2], r4[3] };
                mma16816h(o[pp*2],   a4, b0);
                mma16816h(o[pp*2+1], a4, b1);
            }
        }
    }

    const float lg  = __shfl_sync(0xffffffffu, ol[0], lane & ~3);
    const float lg8 = __shfl_sync(0xffffffffu, ol[2], lane & ~3);
    const float inv0 = 1.f / lg;
    const float inv1 = 1.f / lg8;

    const int r0 = q0 + wid * 16 + g;
    const int r1 = r0 + 8;
#pragma unroll
    for (int nf = 0; nf < 4; nf++) {
        const int dd = nf * 8 + tq * 2;
        *reinterpret_cast<uint32_t*>(out + ((size_t)(b * S_ + r0)) * D_ + h * DH_ + dd) =
            packbf2(o[nf][0] * inv0, o[nf][1] * inv0);
        *reinterpret_cast<uint32_t*>(out + ((size_t)(b * S_ + r1)) * D_ + h * DH_ + dd) =
            packbf2(o[nf][2] * inv1, o[nf][3] * inv1);
    }
}

// ======================= fused out-proj + LN1 + FFN + LN2 [+ next-layer QKV | + head] =======================
// R14 structure (ping-pong overlap). DO_QKV=1: phase 3 computes next-layer QKV.
// DO_QKV=0: last-token CTAs ((blockIdx.x&15)==15) additionally compute the head
// (FC -> softmax -> rebalance) from the LN2 output captured in smem (bit-identical values).
#define FF_SMEM 111104
template<int DO_QKV>
__global__ __launch_bounds__(256)
void ffn2_kernel(const __nv_bfloat16* __restrict__ attnb,
                 const __nv_bfloat16* __restrict__ Wo, const float* __restrict__ ob,
                 const float* __restrict__ Rin,
                 const float* __restrict__ l1g, const float* __restrict__ l1b,
                 const __nv_bfloat16* __restrict__ W1, const float* __restrict__ b1,
                 const __nv_bfloat16* __restrict__ W2, const float* __restrict__ b2,
                 const float* __restrict__ l2g, const float* __restrict__ l2b,
                 const __nv_bfloat16* __restrict__ Wqkv, const float* __restrict__ qkvb,
                 __nv_bfloat16* __restrict__ qo, __nv_bfloat16* __restrict__ ko,
                 __nv_bfloat16* __restrict__ vo,
                 float* __restrict__ hOut,
                 const float* __restrict__ fcw, const float* __restrict__ fcb,
                 float* __restrict__ outp)
{
    extern __shared__ char sm[];
    float* ob_s  = (float*)(sm + 104448);
    float* g1s   = (float*)(sm + 104960);
    float* bb1s  = (float*)(sm + 105472);
    float* b1s   = (float*)(sm + 105984);   // 512 floats
    float* b2s   = (float*)(sm + 108032);
    float* g2s   = (float*)(sm + 108544);
    float* bb2s  = (float*)(sm + 109056);
    float* qb_s  = (float*)(sm + 109568);   // 384 floats (qkv bias) — reused as head buffer when !DO_QKV
    float* lt_s    = qb_s;                  // [128] last-token features
    float* logit_s = qb_s + 128;            // [30] logits

    const int t    = threadIdx.x;
    const int wid  = t >> 5;
    const int lane = t & 31;
    const int g    = lane >> 2;
    const int tq   = lane & 3;
    const int row0 = blockIdx.x * 128;
    const bool headCTA = (!DO_QKV) && ((blockIdx.x & 15) == 15);

    const uint32_t sA  = cvta_s(sm);
    const uint32_t sWa = sA + 34816;   // Wo, then W2 chunks, then Wk
    const uint32_t sWb = sA + 69632;   // W1 chunks, then Wq/Wv

    auto loadW1 = [&](int c) {
#pragma unroll
        for (int i = 0; i < 8; i++) {
            int id = t + (i << 8);
            int r = id >> 4, cc = id & 15;
            cp16(sWb + (r * TSTW + cc * 8) * 2, &W1[(size_t)(c * 128 + r) * 128 + cc * 8]);
        }
    };
    auto loadW2 = [&](int c) {
#pragma unroll
        for (int i = 0; i < 8; i++) {
            int id = t + (i << 8);
            int r = id >> 4, cc = id & 15;
            cp16(sWa + (r * TSTW + cc * 8) * 2, &W2[(size_t)r * 512 + c * 128 + cc * 8]);
        }
    };
    auto loadWq = [&](int c, uint32_t dstbuf) {
#pragma unroll
        for (int i = 0; i < 8; i++) {
            int id = t + (i << 8);
            int r = id >> 4, cc = id & 15;
            cp16(dstbuf + (r * TSTW + cc * 8) * 2, &Wqkv[(size_t)(c * 128 + r) * 128 + cc * 8]);
        }
    };

    // ---- prologue: attnb + Wo (G1); W1[0] (G2); params ----
#pragma unroll
    for (int i = 0; i < 8; i++) {
        int id = t + (i << 8);
        int r = id >> 4, cc = id & 15;
        cp16(sA  + (r * TSTW + cc * 8) * 2, &attnb[(size_t)(row0 + r) * 128 + cc * 8]);
        cp16(sWa + (r * TSTW + cc * 8) * 2, &Wo[(size_t)r * 128 + cc * 8]);
    }
    CP_COMMIT();
    loadW1(0);
    CP_COMMIT();
    b1s[t] = b1[t]; b1s[t + 256] = b1[t + 256];
    if (t < 128) {
        ob_s[t] = ob[t]; g1s[t] = l1g[t]; bb1s[t] = l1b[t];
        b2s[t] = b2[t];  g2s[t] = l2g[t]; bb2s[t] = l2b[t];
    }
    if (DO_QKV && t < 128) {
        qb_s[t] = qkvb[t]; qb_s[t + 128] = qkvb[t + 128]; qb_s[t + 256] = qkvb[t + 256];
    }
    CP_WAIT(1);          // G1 done; G2 in flight
    __syncthreads();

    const int aRow = wid * 16 + (lane & 15);
    const int aColX = (lane >> 4) * 8;
    const int bRow = (lane & 7) + ((lane >> 4) << 3);
    const int bColX = ((lane >> 3) & 1) * 8;
    const int m0 = row0 + wid * 16 + g;
    const int m1 = m0 + 8;
    const int lm0 = wid * 16 + g;
    const int lm1 = lm0 + 8;

    uint32_t afA[8][4];
    float acc1[16][4];

    // ================= PHASE 1: out-projection =================
#pragma unroll
    for (int kf = 0; kf < 8; kf++)
        ldm_x4(afA[kf], sA + (aRow * TSTW + kf * 16 + aColX) * 2);

#pragma unroll
    for (int nf = 0; nf < 16; nf++)
#pragma unroll
        for (int e = 0; e < 4; e++) acc1[nf][e] = 0.f;
#pragma unroll
    for (int kf = 0; kf < 8; kf++) {
#pragma unroll
        for (int np = 0; np < 8; np++) {
            uint32_t r4[4];
            ldm_x4(r4, sWa + ((np * 16 + bRow) * TSTW + kf * 16 + bColX) * 2);
            uint32_t b0f[2] = { r4[0], r4[1] }, b1f[2] = { r4[2], r4[3] };
            mma16816(acc1[np*2],   afA[kf], b0f);
            mma16816(acc1[np*2+1], afA[kf], b1f);
        }
    }
    __syncthreads();
    loadW2(0); CP_COMMIT();                // G3 -> sWa (overlaps epilogue)

    // bias + residual(Rin) + LN1 -> hOut (fp32) + As (bf16)
    {
        float s0 = 0.f, sq0 = 0.f, s1 = 0.f, sq1 = 0.f;
#pragma unroll
        for (int nf = 0; nf < 16; nf++) {
            const int cc = nf * 8 + tq * 2;
            float2 r0 = *reinterpret_cast<const float2*>(Rin + (size_t)m0 * 128 + cc);
            float2 r1 = *reinterpret_cast<const float2*>(Rin + (size_t)m1 * 128 + cc);
            float v0 = acc1[nf][0] + ob_s[cc]     + r0.x;
            float v1 = acc1[nf][1] + ob_s[cc + 1] + r0.y;
            float v2 = acc1[nf][2] + ob_s[cc]     + r1.x;
            float v3 = acc1[nf][3] + ob_s[cc + 1] + r1.y;
            acc1[nf][0] = v0; acc1[nf][1] = v1; acc1[nf][2] = v2; acc1[nf][3] = v3;
            s0 += v0 + v1; sq0 += v0*v0 + v1*v1;
            s1 += v2 + v3; sq1 += v2*v2 + v3*v3;
        }
        s0  += __shfl_xor_sync(0xffffffffu, s0, 1);  s0  += __shfl_xor_sync(0xffffffffu, s0, 2);
        sq0 += __shfl_xor_sync(0xffffffffu, sq0, 1); sq0 += __shfl_xor_sync(0xffffffffu, sq0, 2);
        s1  += __shfl_xor_sync(0xffffffffu, s1, 1);  s1  += __shfl_xor_sync(0xffffffffu, s1, 2);
        sq1 += __shfl_xor_sync(0xffffffffu, sq1, 1); sq1 += __shfl_xor_sync(0xffffffffu, sq1, 2);
        float mean0 = s0 * (1.f/128.f);
        float mean1 = s1 * (1.f/128.f);
        float rstd0 = rsqrtf(sq0 * (1.f/128.f) - mean0*mean0 + 1e-5f);
        float rstd1 = rsqrtf(sq1 * (1.f/128.f) - mean1*mean1 + 1e-5f);
#pragma unroll
        for (int nf = 0; nf < 16; nf++) {
            const int cc = nf * 8 + tq * 2;
            float y0 = (acc1[nf][0] - mean0) * rstd0 * g1s[cc]   + bb1s[cc];
            float y1 = (acc1[nf][1] - mean0) * rstd0 * g1s[cc+1] + bb1s[cc+1];
            float y2 = (acc1[nf][2] - mean1) * rstd1 * g1s[cc]   + bb1s[cc];
            float y3 = (acc1[nf][3] - mean1) * rstd1 * g1s[cc+1] + bb1s[cc+1];
            *reinterpret_cast<float2*>(hOut + (size_t)m0 * 128 + cc) = make_float2(y0, y1);
            *reinterpret_cast<float2*>(hOut + (size_t)m1 * 128 + cc) = make_float2(y2, y3);
            asm volatile("st.shared.b32 [%0], %1;" :: "r"(sA + (lm0 * TSTW + cc) * 2), "r"(packbf2(y0, y1)));
            asm volatile("st.shared.b32 [%0], %1;" :: "r"(sA + (lm1 * TSTW + cc) * 2), "r"(packbf2(y2, y3)));
        }
    }
    __syncthreads();                       // As = LN1 output (bf16)

    // ================= PHASE 2: FFN ping-pong (R14) =================
#pragma unroll
    for (int kf = 0; kf < 8; kf++)
        ldm_x4(afA[kf], sA + (aRow * TSTW + kf * 16 + aColX) * 2);

    float acc2[16][4];
#pragma unroll
    for (int nf = 0; nf < 16; nf++)
#pragma unroll
        for (int e = 0; e < 4; e++) acc2[nf][e] = 0.f;

    for (int c = 0; c < 4; c++) {
        CP_WAIT(1);                        // W1[c] (sWb) ready
        __syncthreads();

        // GEMM1 (W2[c] loading into sWa in background)
#pragma unroll
        for (int nf = 0; nf < 16; nf++)
#pragma unroll
            for (int e = 0; e < 4; e++) acc1[nf][e] = 0.f;
#pragma unroll
        for (int kf = 0; kf < 8; kf++) {
#pragma unroll
            for (int np = 0; np < 8; np++) {
                uint32_t r4[4];
                ldm_x4(r4, sWb + ((np * 16 + bRow) * TSTW + kf * 16 + bColX) * 2);
                uint32_t b0f[2] = { r4[0], r4[1] }, b1f[2] = { r4[2], r4[3] };
                mma16816(acc1[np*2],   afA[kf], b0f);
                mma16816(acc1[np*2+1], afA[kf], b1f);
            }
        }
        __syncthreads();                   // done reading sWb
        if (c < 3)           { loadW1(c + 1);   CP_COMMIT(); }
        else if (DO_QKV)     { loadWq(0, sWb);  CP_COMMIT(); }   // Wq -> sWb
        if (c < 3 || DO_QKV) CP_WAIT(1); else CP_WAIT(0);        // W2[c] (sWa) ready
        __syncthreads();

        // relu + bias -> GEMM2 A k-frags
        uint32_t a1[8][4];
#pragma unroll
        for (int nf = 0; nf < 16; nf++) {
            const int col = c * 128 + nf * 8 + tq * 2;
            float v0 = fmaxf(acc1[nf][0] + b1s[col],     0.f);
            float v1 = fmaxf(acc1[nf][1] + b1s[col + 1], 0.f);
            float v2 = fmaxf(acc1[nf][2] + b1s[col],     0.f);
            float v3 = fmaxf(acc1[nf][3] + b1s[col + 1], 0.f);
            const int kf2 = nf >> 1;
            if ((nf & 1) == 0) { a1[kf2][0] = packbf2(v0, v1); a1[kf2][1] = packbf2(v2, v3); }
            else               { a1[kf2][2] = packbf2(v0, v1); a1[kf2][3] = packbf2(v2, v3); }
        }

        // GEMM2
#pragma unroll
        for (int kf = 0; kf < 8; kf++) {
#pragma unroll
            for (int np = 0; np < 8; np++) {
                uint32_t r4[4];
                ldm_x4(r4, sWa + ((np * 16 + bRow) * TSTW + kf * 16 + bColX) * 2);
                uint32_t b0f[2] = { r4[0], r4[1] }, b1f[2] = { r4[2], r4[3] };
                mma16816(acc2[np*2],   a1[kf], b0f);
                mma16816(acc2[np*2+1], a1[kf], b1f);
            }
        }
        __syncthreads();                   // done reading sWa
        if (c < 3)           { loadW2(c + 1);  CP_COMMIT(); }
        else if (DO_QKV)     { loadWq(1, sWa); CP_COMMIT(); }    // Wk -> sWa
    }

    // ---- bias + residual(h=LN1) + LN2 -> hOut (+ As bf16 if QKV; capture last-token row if head) ----
    {
        float s0 = 0.f, sq0 = 0.f, s1 = 0.f, sq1 = 0.f;
#pragma unroll
        for (int nf = 0; nf < 16; nf++) {
            const int cc = nf * 8 + tq * 2;
            float2 r0 = *reinterpret_cast<const float2*>(hOut + (size_t)m0 * 128 + cc);
            float2 r1 = *reinterpret_cast<const float2*>(hOut + (size_t)m1 * 128 + cc);
            float v0 = acc2[nf][0] + b2s[cc]     + r0.x;
            float v1 = acc2[nf][1] + b2s[cc + 1] + r0.y;
            float v2 = acc2[nf][2] + b2s[cc]     + r1.x;
            float v3 = acc2[nf][3] + b2s[cc + 1] + r1.y;
            acc2[nf][0] = v0; acc2[nf][1] = v1; acc2[nf][2] = v2; acc2[nf][3] = v3;
            s0 += v0 + v1; sq0 += v0*v0 + v1*v1;
            s1 += v2 + v3; sq1 += v2*v2 + v3*v3;
        }
        s0  += __shfl_xor_sync(0xffffffffu, s0, 1);  s0  += __shfl_xor_sync(0xffffffffu, s0, 2);
        sq0 += __shfl_xor_sync(0xffffffffu, sq0, 1); sq0 += __shfl_xor_sync(0xffffffffu, sq0, 2);
        s1  += __shfl_xor_sync(0xffffffffu, s1, 1);  s1  += __shfl_xor_sync(0xffffffffu, s1, 2);
        sq1 += __shfl_xor_sync(0xffffffffu, sq1, 1); sq1 += __shfl_xor_sync(0xffffffffu, sq1, 2);
        float mean0 = s0 * (1.f/128.f);
        float mean1 = s1 * (1.f/128.f);
        float rstd0 = rsqrtf(sq0 * (1.f/128.f) - mean0*mean0 + 1e-5f);
        float rstd1 = rsqrtf(sq1 * (1.f/128.f) - mean1*mean1 + 1e-5f);
        const bool cap = headCTA && (wid == 7) && (g == 7);   // local row 127
#pragma unroll
        for (int nf = 0; nf < 16; nf++) {
            const int cc = nf * 8 + tq * 2;
            float y0 = (acc2[nf][0] - mean0) * rstd0 * g2s[cc]   + bb2s[cc];
            float y1 = (acc2[nf][1] - mean0) * rstd0 * g2s[cc+1] + bb2s[cc+1];
            float y2 = (acc2[nf][2] - mean1) * rstd1 * g2s[cc]   + bb2s[cc];
            float y3 = (acc2[nf][3] - mean1) * rstd1 * g2s[cc+1] + bb2s[cc+1];
            *reinterpret_cast<float2*>(hOut + (size_t)m0 * 128 + cc) = make_float2(y0, y1);
            *reinterpret_cast<float2*>(hOut + (size_t)m1 * 128 + cc) = make_float2(y2, y3);
            if (DO_QKV) {
                asm volatile("st.shared.b32 [%0], %1;" :: "r"(sA + (lm0 * TSTW + cc) * 2), "r"(packbf2(y0, y1)));
                asm volatile("st.shared.b32 [%0], %1;" :: "r"(sA + (lm1 * TSTW + cc) * 2), "r"(packbf2(y2, y3)));
            } else if (cap) {
                lt_s[cc] = y2; lt_s[cc + 1] = y3;   // row m1 = row0+127 = last token
            }
        }
    }

    if (!DO_QKV) {
        // ---- head (last-token CTAs only; blockIdx-uniform branch) ----
        if (headCTA) {
            __syncthreads();
            if (t < OUT_) {
                float acc = fcb[t];
                for (int d = 0; d < D_; d++) acc += lt_s[d] * fcw[t * D_ + d];
                logit_s[t] = acc;
            }
            __syncthreads();
            if (t == 0) {
                const float UB = 0.3f, LB = 0.0f;
                const int b = blockIdx.x >> 4;
                float wv[OUT_], old[OUT_], wc[OUT_], res[OUT_];
                float mx = -1e30f;
                for (int o = 0; o < OUT_; o++) mx = fmaxf(mx, logit_s[o]);
                float sum = 0.f;
                for (int o = 0; o < OUT_; o++) { wv[o] = expf(logit_s[o] - mx); sum += wv[o]; }
                float inv = 1.f / sum;
                for (int o = 0; o < OUT_; o++) wv[o] *= inv;
                bool done = false;
                for (int o = 0; o < OUT_; o++) {
                    old[o] = wv[o];
                    wc[o]  = fminf(fmaxf(wv[o], LB), UB);
                    res[o] = wv[o];
                }
                for (int it = 0; it < 16; it++) {
                    float leftover = 0.f;
                    for (int o = 0; o < OUT_; o++) leftover += old[o] - wc[o];
                    float denom = 0.f;
                    float noms[OUT_];
                    for (int o = 0; o < OUT_; o++) {
                        noms[o] = (wc[o] != UB) ? wc[o] : 0.f;
                        denom += noms[o];
                    }
                    if (denom == 0.f) denom = 1.f;
                    float cand[OUT_];
                    bool any = false;
                    for (int o = 0; o < OUT_; o++) {
                        cand[o] = wc[o] + leftover * noms[o] / denom;
                        if (cand[o] > UB) any = true;
                    }
                    if (!done)
                        for (int o = 0; o < OUT_; o++) res[o] = cand[o];
                    done = done || !any;
                    if (!done) {
                        for (int o = 0; o < OUT_; o++) {
                            old[o] = cand[o];
                            wc[o]  = fminf(fmaxf(cand[o], LB), UB);
                        }
                    }
                }
                for (int o = 0; o < OUT_; o++) outp[b * OUT_ + o] = res[o];
            }
        }
        return;
    }
    __syncthreads();                       // As = LN2 output (bf16)

    // ================= PHASE 3: next-layer QKV =================
#pragma unroll
    for (int kf = 0; kf < 8; kf++)
        ldm_x4(afA[kf], sA + (aRow * TSTW + kf * 16 + aColX) * 2);

    const int b0i = m0 >> 11, s0i = m0 & 2047;
    const int b1i = m1 >> 11, s1i = m1 & 2047;

#pragma unroll
    for (int c3 = 0; c3 < 3; c3++) {
        if (c3 < 2) CP_WAIT(1); else CP_WAIT(0);   // chunk c3 ready
        __syncthreads();
        const uint32_t wbuf = (c3 == 1) ? sWa : sWb;

#pragma unroll
        for (int nf = 0; nf < 16; nf++)
#pragma unroll
            for (int e = 0; e < 4; e++) acc1[nf][e] = 0.f;
#pragma unroll
        for (int kf = 0; kf < 8; kf++) {
#pragma unroll
            for (int np = 0; np < 8; np++) {
                uint32_t r4[4];
                ldm_x4(r4, wbuf + ((np * 16 + bRow) * TSTW + kf * 16 + bColX) * 2);
                uint32_t b0f[2] = { r4[0], r4[1] }, b1f[2] = { r4[2], r4[3] };
                mma16816(acc1[np*2],   afA[kf], b0f);
                mma16816(acc1[np*2+1], afA[kf], b1f);
            }
        }
        __syncthreads();
        if (c3 == 0) { loadWq(2, sWb); CP_COMMIT(); }   // Wv -> sWb during q epilogue

        __nv_bfloat16* dst = (c3 == 0) ? qo : ((c3 == 1) ? ko : vo);
#pragma unroll
        for (int nf = 0; nf < 16; nf++) {
            const int cc = nf * 8 + tq * 2;
            float v0 = acc1[nf][0] + qb_s[c3 * 128 + cc];
            float v1 = acc1[nf][1] + qb_s[c3 * 128 + cc + 1];
            float v2 = acc1[nf][2] + qb_s[c3 * 128 + cc];
            float v3 = acc1[nf][3] + qb_s[c3 * 128 + cc + 1];
            if (c3 == 0) { v0 *= QSCALE; v1 *= QSCALE; v2 *= QSCALE; v3 *= QSCALE; }
            const int hh = cc >> 5, dd = cc & 31;
            uint32_t p0, p1;
            if (c3 == 2) { p0 = packhf2(v0, v1); p1 = packhf2(v2, v3); }
            else         { p0 = packbf2(v0, v1); p1 = packbf2(v2, v3); }
            *reinterpret_cast<uint32_t*>(dst + ((size_t)(b0i * H_ + hh) * S_ + s0i) * DH_ + dd) = p0;
            *reinterpret_cast<uint32_t*>(dst + ((size_t)(b1i * H_ + hh) * S_ + s1i) * DH_ + dd) = p1;
        }
    }
}

// ======================= launch =======================
extern "C" void kernel_launch(void* const* d_in, const int* in_sizes, int n_in,
                              void* d_out, int out_size)
{
    const float* x   = (const float*)d_in[0];
    const float* ipw = (const float*)d_in[1];
    const float* ipb = (const float*)d_in[2];
    const float* ow  = (const float*)d_in[3];
    const float* ob  = (const float*)d_in[4];
    const float* l1g = (const float*)d_in[5];
    const float* l1b = (const float*)d_in[6];
    const float* f1w = (const float*)d_in[7];
    const float* f1b = (const float*)d_in[8];
    const float* f2w = (const float*)d_in[9];
    const float* f2b = (const float*)d_in[10];
    const float* l2g = (const float*)d_in[11];
    const float* l2b = (const float*)d_in[12];
    const float* fcw = (const float*)d_in[13];
    const float* fcb = (const float*)d_in[14];

    __nv_bfloat16 *qb, *kb, *vb, *attnb, *hb, *wip, *wout, *wf1, *wf2;
    float *h;
    cudaGetSymbolAddress((void**)&qb,    g_qb);
    cudaGetSymbolAddress((void**)&kb,    g_kb);
    cudaGetSymbolAddress((void**)&vb,    g_vb);
    cudaGetSymbolAddress((void**)&attnb, g_attnb);
    cudaGetSymbolAddress((void**)&hb,    g_hb);
    cudaGetSymbolAddress((void**)&h,     g_h);
    cudaGetSymbolAddress((void**)&wip,   g_wip);
    cudaGetSymbolAddress((void**)&wout,  g_wout);
    cudaGetSymbolAddress((void**)&wf1,   g_wf1);
    cudaGetSymbolAddress((void**)&wf2,   g_wf2);

    cudaFuncSetAttribute(qkv_kernel,     cudaFuncAttributeMaxDynamicSharedMemorySize, MM_SMEM);
    cudaFuncSetAttribute(attn_kernel,    cudaFuncAttributeMaxDynamicSharedMemorySize, AT_SMEM);
    cudaFuncSetAttribute(ffn2_kernel<0>, cudaFuncAttributeMaxDynamicSharedMemorySize, FF_SMEM);
    cudaFuncSetAttribute(ffn2_kernel<1>, cudaFuncAttributeMaxDynamicSharedMemorySize, FF_SMEM);

    // all weight conversions in ONE launch; x conversion in another
    cvtw_kernel<<<(NW0+NW1+NW2+NW3)/1024, 256>>>(ipw, wip, ow, wout, f1w, wf1, f2w, wf2);
    cvt_kernel<<<(M_*D_)/1024, 256>>>(x, hb, M_*D_);

    // layer-0 QKV (from x)
    qkv_kernel<<<dim3(3, M_/128), 256, MM_SMEM>>>(
        hb, wip, ipb, qb, kb, vb);

    for (int l = 0; l < L_; l++) {
        const float* hinF = (l == 0) ? x : h;

        // flash attention
        attn_kernel<<<dim3(S_/128, B_*H_), 256, AT_SMEM>>>(qb, kb, vb, attnb);

        if (l < 3) {
            // fused out-proj + LN1 + FFN + LN2 + next-layer QKV
            ffn2_kernel<1><<<M_/128, 256, FF_SMEM>>>(
                attnb, wout + (size_t)l*D_*D_, ob + (size_t)l*D_,
                hinF, l1g + (size_t)l*D_, l1b + (size_t)l*D_,
                wf1 + (size_t)l*FF_*D_, f1b + (size_t)l*FF_,
                wf2 + (size_t)l*D_*FF_, f2b + (size_t)l*D_,
                l2g + (size_t)l*D_, l2b + (size_t)l*D_,
                wip + (size_t)(l+1)*3*D_*D_, ipb + (size_t)(l+1)*3*D_,
                qb, kb, vb, h, nullptr, nullptr, nullptr);
        } else {
            // final layer: fused out-proj + LN1 + FFN + LN2 + head
            ffn2_kernel<0><<<M_/128, 256, FF_SMEM>>>(
                attnb, wout + (size_t)l*D_*D_, ob + (size_t)l*D_,
                hinF, l1g + (size_t)l*D_, l1b + (size_t)l*D_,
                wf1 + (size_t)l*FF_*D_, f1b + (size_t)l*FF_,
                wf2 + (size_t)l*D_*FF_, f2b + (size_t)l*D_,
                l2g + (size_t)l*D_, l2b + (size_t)l*D_,
                nullptr, nullptr, nullptr, nullptr, nullptr, h,
                fcw, fcb, (float*)d_out);
        }
    }
}